// round 7
// baseline (speedup 1.0000x reference)
#include <cuda_runtime.h>
#include <cstdint>

#define NB 32
#define C  512
#define K  64
#define P  3136
#define CK (C*K)        // 32768
#define PSPLIT 2
#define PCH (P/PSPLIT)  // 1568

// A tile: [4 kk][128 rows][20 floats], kk stride 2576 (== 16 mod 32)
// B tile: [4 kk][ 64 rows][20 floats], kk stride 1296 (== 16 mod 32)
#define AKS 2576
#define BKS 1296
#define A_FLOATS (4 * AKS)   // 10304
#define B_FLOATS (4 * BKS)   // 5184

// Scratch (device globals; allocation forbidden elsewhere)
__device__ __align__(256) float g_a[(size_t)NB * K * P];          // softmax probs ~25.7MB
__device__ __align__(256) float g_part[(size_t)PSPLIT * NB * CK]; // vlad partials
__device__ __align__(256) float g_asumP[PSPLIT * NB * K];
__device__ __align__(256) float g_rowsq[NB * C];

__device__ __forceinline__ float tf32_rn(float x) {
    uint32_t u; asm("cvt.rna.tf32.f32 %0, %1;" : "=r"(u) : "f"(x));
    return __uint_as_float(u);
}
__device__ __forceinline__ uint32_t fu(float x) { return __float_as_uint(x); }

__device__ __forceinline__ void mma8(float acc[4], uint32_t a0, uint32_t a1,
                                     uint32_t a2, uint32_t a3,
                                     uint32_t b0, uint32_t b1) {
    asm volatile(
        "mma.sync.aligned.m16n8k8.row.col.f32.tf32.tf32.f32 "
        "{%0,%1,%2,%3}, {%4,%5,%6,%7}, {%8,%9}, {%0,%1,%2,%3};"
        : "+f"(acc[0]), "+f"(acc[1]), "+f"(acc[2]), "+f"(acc[3])
        : "r"(a0), "r"(a1), "r"(a2), "r"(a3), "r"(b0), "r"(b1));
}

// Store one element (row, k) split into hi/lo, interleaved layout, one STS.64.
__device__ __forceinline__ void store_elem(float* tile, int ks, int row, int k, float v) {
    const float h = tf32_rn(v);
    *(float2*)(tile + (k >> 3) * ks + row * 20 + 4 * (k & 3) + 2 * ((k >> 2) & 1))
        = make_float2(h, v - h);
}

// CTA tile 128(M) x 64(N), chunk K=32. Warps 4(M) x 2(N), per-warp 32x32.
__device__ __forceinline__ void compute_chunk(
    const float* sA, const float* sB, float acc[2][4][4],
    int wm, int wn, int g, int t)
{
    #pragma unroll
    for (int kk = 0; kk < 4; kk++) {
        float4 afr[2][2];   // [mt][row-half]: {hi_t, lo_t, hi_t4, lo_t4}
        #pragma unroll
        for (int mt = 0; mt < 2; mt++) {
            const int r0 = wm * 32 + mt * 16 + g;
            afr[mt][0] = *(const float4*)(sA + kk * AKS + r0 * 20 + 4 * t);
            afr[mt][1] = *(const float4*)(sA + kk * AKS + (r0 + 8) * 20 + 4 * t);
        }
        #pragma unroll
        for (int nt = 0; nt < 4; nt++) {
            const int rb = wn * 32 + nt * 8 + g;
            const float4 bf = *(const float4*)(sB + kk * BKS + rb * 20 + 4 * t);
            const uint32_t bh0 = fu(bf.x), bl0 = fu(bf.y);
            const uint32_t bh1 = fu(bf.z), bl1 = fu(bf.w);
            #pragma unroll
            for (int mt = 0; mt < 2; mt++) {
                const uint32_t ah0 = fu(afr[mt][0].x), ah1 = fu(afr[mt][1].x);
                const uint32_t ah2 = fu(afr[mt][0].z), ah3 = fu(afr[mt][1].z);
                const uint32_t al0 = fu(afr[mt][0].y), al1 = fu(afr[mt][1].y);
                const uint32_t al2 = fu(afr[mt][0].w), al3 = fu(afr[mt][1].w);
                mma8(acc[mt][nt], ah0, ah1, ah2, ah3, bh0, bh1);  // hi*hi
                mma8(acc[mt][nt], ah0, ah1, ah2, ah3, bl0, bl1);  // hi*lo
                mma8(acc[mt][nt], al0, al1, al2, al3, bh0, bh1);  // lo*hi
            }
        }
    }
}

// ===================== GEMM1: logits + softmax =====================
// grid (25, 32). M=128 pixels x N=64 clusters; contraction C=512, 16 chunks of 32.
// pool floats: sA@0 (10304), sB@10304 (5184), bias@15488 (64) = 15552 floats.
// sL [128][65] overlays sA in epilogue.
#define G1_SMEM (15552 * 4)
__global__ __launch_bounds__(256, 2) void k_logits_tc(
    const float* __restrict__ x, const float* __restrict__ w,
    const float* __restrict__ bias)
{
    extern __shared__ float pool[];
    float* sA = pool;
    float* sB = pool + A_FLOATS;
    float* sBias = pool + A_FLOATS + B_FLOATS;
    float* sL = pool;                 // epilogue overlay [128][65]

    const int tid = threadIdx.x, lane = tid & 31, wid = tid >> 5;
    const int g = lane >> 2, t = lane & 3;
    const int wm = wid & 3, wn = wid >> 2;
    const int n = blockIdx.y, p0 = blockIdx.x * 128;

    if (tid < 64) sBias[tid] = bias[tid];

    const float* xn = x + (size_t)n * C * P;
    const int pl = tid & 127;            // pixel column this thread stages
    const bool pok = (p0 + pl) < P;
    const int cb = tid >> 7;             // 0/1

    float acc[2][4][4];
    #pragma unroll
    for (int mt = 0; mt < 2; mt++)
        #pragma unroll
        for (int nt = 0; nt < 4; nt++)
            #pragma unroll
            for (int q = 0; q < 4; q++) acc[mt][nt][q] = 0.f;

    float xv[16], wv[8];
    #pragma unroll
    for (int r = 0; r < 16; r++)
        xv[r] = pok ? xn[(size_t)(cb + 2 * r) * P + p0 + pl] : 0.f;
    #pragma unroll
    for (int r = 0; r < 8; r++)
        wv[r] = w[(size_t)(wid + 8 * r) * C + lane];

    for (int i = 0; i < 16; i++) {
        if (i) __syncthreads();
        #pragma unroll
        for (int r = 0; r < 16; r++)
            store_elem(sA, AKS, pl, cb + 2 * r, xv[r]);   // row=pixel, k=c
        #pragma unroll
        for (int r = 0; r < 8; r++)
            store_elem(sB, BKS, wid + 8 * r, lane, wv[r]);
        __syncthreads();
        if (i + 1 < 16) {
            const int c0 = (i + 1) * 32;
            #pragma unroll
            for (int r = 0; r < 16; r++)
                xv[r] = pok ? xn[(size_t)(c0 + cb + 2 * r) * P + p0 + pl] : 0.f;
            #pragma unroll
            for (int r = 0; r < 8; r++)
                wv[r] = w[(size_t)(wid + 8 * r) * C + c0 + lane];
        }
        compute_chunk(sA, sB, acc, wm, wn, g, t);
    }

    // epilogue: logits -> sL, softmax over k per pixel
    __syncthreads();
    #pragma unroll
    for (int mt = 0; mt < 2; mt++) {
        const int pr = wm * 32 + mt * 16 + g;
        #pragma unroll
        for (int nt = 0; nt < 4; nt++) {
            const int k0 = wn * 32 + nt * 8 + 2 * t;
            sL[pr * 65 + k0]           = acc[mt][nt][0] + sBias[k0];
            sL[pr * 65 + k0 + 1]       = acc[mt][nt][1] + sBias[k0 + 1];
            sL[(pr + 8) * 65 + k0]     = acc[mt][nt][2] + sBias[k0];
            sL[(pr + 8) * 65 + k0 + 1] = acc[mt][nt][3] + sBias[k0 + 1];
        }
    }
    __syncthreads();
    if (tid < 128 && p0 + tid < P) {
        const float* row = sL + tid * 65;
        float v[64], m = -1e30f;
        #pragma unroll
        for (int k = 0; k < 64; k++) { v[k] = row[k]; m = fmaxf(m, v[k]); }
        float s = 0.f;
        #pragma unroll
        for (int k = 0; k < 64; k++) { v[k] = __expf(v[k] - m); s += v[k]; }
        const float inv = 1.f / s;
        float* ga = g_a + (size_t)n * K * P + p0 + tid;
        #pragma unroll
        for (int k = 0; k < 64; k++) ga[(size_t)k * P] = v[k] * inv;
    }
}

// ===================== GEMM2: vlad partials (+ fused asum) =====================
// grid (4, PSPLIT, 32). M=128 c x N=64 k; contraction 1568 p, 49 chunks of 32.
#define G2_SMEM ((A_FLOATS + B_FLOATS) * 4)
__global__ __launch_bounds__(256, 2) void k_vlad_tc(const float* __restrict__ x)
{
    extern __shared__ float pool2[];
    float* sA = pool2;
    float* sB = pool2 + A_FLOATS;

    const int tid = threadIdx.x, lane = tid & 31, wid = tid >> 5;
    const int g = lane >> 2, t = lane & 3;
    const int wm = wid & 3, wn = wid >> 2;
    const int n = blockIdx.z, sp = blockIdx.y, c0 = blockIdx.x * 128;
    const bool do_asum = (blockIdx.x == 0);

    const float* xn = x + ((size_t)n * C + c0) * P;
    const float* an = g_a + (size_t)n * K * P;
    const int pb0 = sp * PCH;

    float acc[2][4][4];
    #pragma unroll
    for (int mt = 0; mt < 2; mt++)
        #pragma unroll
        for (int nt = 0; nt < 4; nt++)
            #pragma unroll
            for (int q = 0; q < 4; q++) acc[mt][nt][q] = 0.f;

    float asumL[8];
    #pragma unroll
    for (int r = 0; r < 8; r++) asumL[r] = 0.f;

    float xv[16], av[8];
    #pragma unroll
    for (int r = 0; r < 16; r++)
        xv[r] = xn[(size_t)(wid + 8 * r) * P + pb0 + lane];
    #pragma unroll
    for (int r = 0; r < 8; r++)
        av[r] = an[(size_t)(wid + 8 * r) * P + pb0 + lane];

    for (int i = 0; i < 49; i++) {
        if (i) __syncthreads();
        #pragma unroll
        for (int r = 0; r < 16; r++)
            store_elem(sA, AKS, wid + 8 * r, lane, xv[r]);
        #pragma unroll
        for (int r = 0; r < 8; r++) {
            store_elem(sB, BKS, wid + 8 * r, lane, av[r]);
            if (do_asum) asumL[r] += av[r];
        }
        __syncthreads();
        if (i + 1 < 49) {
            const int pb = pb0 + (i + 1) * 32;
            #pragma unroll
            for (int r = 0; r < 16; r++)
                xv[r] = xn[(size_t)(wid + 8 * r) * P + pb + lane];
            #pragma unroll
            for (int r = 0; r < 8; r++)
                av[r] = an[(size_t)(wid + 8 * r) * P + pb + lane];
        }
        compute_chunk(sA, sB, acc, wm, wn, g, t);
    }

    float* gp = g_part + ((size_t)sp * NB + n) * CK;
    #pragma unroll
    for (int mt = 0; mt < 2; mt++) {
        const int cr = c0 + wm * 32 + mt * 16 + g;
        #pragma unroll
        for (int nt = 0; nt < 4; nt++) {
            const int k0 = wn * 32 + nt * 8 + 2 * t;
            *(float2*)(gp + (size_t)cr * 64 + k0) =
                make_float2(acc[mt][nt][0], acc[mt][nt][1]);
            *(float2*)(gp + (size_t)(cr + 8) * 64 + k0) =
                make_float2(acc[mt][nt][2], acc[mt][nt][3]);
        }
    }

    if (do_asum) {
        #pragma unroll
        for (int r = 0; r < 8; r++) {
            float s = asumL[r];
            #pragma unroll
            for (int o = 16; o > 0; o >>= 1) s += __shfl_xor_sync(0xffffffffu, s, o);
            if (lane == 0) g_asumP[(sp * NB + n) * K + wid + 8 * r] = s;
        }
    }
}

// --------------- combine partials + centroid correction + intra-norm
// 1 warp per (n,c) row; thread handles k=lane and k=lane+32.
__global__ __launch_bounds__(256) void k_combine_intra(
    const float* __restrict__ cent, float* __restrict__ out)
{
    const int row = blockIdx.x * 8 + (threadIdx.x >> 5);   // n*512 + c
    const int n = row >> 9, c = row & 511;
    const int lane = threadIdx.x & 31;

    const size_t b0 = (size_t)n * CK + c * 64;
    const size_t b1 = ((size_t)NB + n) * CK + c * 64;

    float v0 = g_part[b0 + lane] + g_part[b1 + lane]
             - cent[c * 64 + lane]
               * (g_asumP[n * K + lane] + g_asumP[(NB + n) * K + lane]);
    float v1 = g_part[b0 + lane + 32] + g_part[b1 + lane + 32]
             - cent[c * 64 + lane + 32]
               * (g_asumP[n * K + lane + 32] + g_asumP[(NB + n) * K + lane + 32]);

    float sq = v0 * v0 + v1 * v1;
    #pragma unroll
    for (int o = 16; o > 0; o >>= 1) sq += __shfl_xor_sync(0xffffffffu, sq, o);

    const float denom = fmaxf(sqrtf(sq), 1e-12f);
    const float inv = 1.f / denom;
    out[(size_t)n * CK + c * 64 + lane]      = v0 * inv;
    out[(size_t)n * CK + c * 64 + lane + 32] = v1 * inv;
    if (lane == 0) g_rowsq[row] = sq * inv * inv;
}

// ------------------------------------------ global L2-norm per n
__global__ __launch_bounds__(256) void k_final(float* __restrict__ out) {
    const int n = blockIdx.x;
    const int t = threadIdx.x;
    __shared__ float red[256];
    red[t] = g_rowsq[n * 512 + t] + g_rowsq[n * 512 + 256 + t];
    __syncthreads();
    for (int o = 128; o > 0; o >>= 1) {
        if (t < o) red[t] += red[t + o];
        __syncthreads();
    }
    __shared__ float inv;
    if (t == 0) inv = 1.f / fmaxf(sqrtf(red[0]), 1e-12f);
    __syncthreads();
    float* v = out + (size_t)n * CK;
    for (int j = t; j < CK; j += 256) v[j] *= inv;
}

extern "C" void kernel_launch(void* const* d_in, const int* in_sizes, int n_in,
                              void* d_out, int out_size) {
    const float* x    = (const float*)d_in[0];   // (32,512,56,56)
    const float* cent = (const float*)d_in[1];   // (64,512)
    const float* w    = (const float*)d_in[2];   // (64,512)
    const float* b    = (const float*)d_in[3];   // (64,)
    float* out = (float*)d_out;                  // (32, 32768)

    cudaFuncSetAttribute(k_logits_tc, cudaFuncAttributeMaxDynamicSharedMemorySize, G1_SMEM);
    cudaFuncSetAttribute(k_vlad_tc,   cudaFuncAttributeMaxDynamicSharedMemorySize, G2_SMEM);

    k_logits_tc<<<dim3(25, 32), 256, G1_SMEM>>>(x, w, b);
    k_vlad_tc<<<dim3(4, PSPLIT, NB), 256, G2_SMEM>>>(x);
    k_combine_intra<<<NB * C / 8, 256>>>(cent, out);
    k_final<<<NB, 256>>>(out);
}

// round 9
// speedup vs baseline: 1.5297x; 1.5297x over previous
#include <cuda_runtime.h>
#include <cuda_fp16.h>
#include <cstdint>

#define NB 32
#define C  512
#define K  64
#define P  3136
#define CK (C*K)        // 32768
#define PSPLIT 2
#define PCH (P/PSPLIT)  // 1568

// Scratch (device globals; allocation forbidden elsewhere)
__device__ __align__(256) float g_a[(size_t)NB * K * P];          // softmax probs ~25.7MB
__device__ __align__(256) float g_part[(size_t)PSPLIT * NB * CK]; // vlad partials
__device__ __align__(256) float g_asumP[PSPLIT * NB * K];
__device__ __align__(256) float g_rowsq[NB * C];
__device__ __align__(256) float g_inv[NB];

__device__ __forceinline__ float tf32_rn(float x) {
    uint32_t u; asm("cvt.rna.tf32.f32 %0, %1;" : "=r"(u) : "f"(x));
    return __uint_as_float(u);
}
__device__ __forceinline__ uint32_t fu(float x) { return __float_as_uint(x); }

__device__ __forceinline__ void mma8_tf32(float acc[4], const uint32_t a[4],
                                          uint32_t b0, uint32_t b1) {
    asm volatile(
        "mma.sync.aligned.m16n8k8.row.col.f32.tf32.tf32.f32 "
        "{%0,%1,%2,%3}, {%4,%5,%6,%7}, {%8,%9}, {%0,%1,%2,%3};"
        : "+f"(acc[0]), "+f"(acc[1]), "+f"(acc[2]), "+f"(acc[3])
        : "r"(a[0]), "r"(a[1]), "r"(a[2]), "r"(a[3]), "r"(b0), "r"(b1));
}
__device__ __forceinline__ void mma16_f16(float acc[4], uint32_t a0, uint32_t a1,
                                          uint32_t a2, uint32_t a3,
                                          uint32_t b0, uint32_t b1) {
    asm volatile(
        "mma.sync.aligned.m16n8k16.row.col.f32.f16.f16.f32 "
        "{%0,%1,%2,%3}, {%4,%5,%6,%7}, {%8,%9}, {%0,%1,%2,%3};"
        : "+f"(acc[0]), "+f"(acc[1]), "+f"(acc[2]), "+f"(acc[3])
        : "r"(a0), "r"(a1), "r"(a2), "r"(a3), "r"(b0), "r"(b1));
}

// ===================== GEMM1 (round-6 proven): tf32 3x, logits + softmax =====
// Shared compute: CTA tile 128(M) x 64(N), chunk K=32. Warps 4(M) x 2(N).
template <int SA>
__device__ __forceinline__ void compute_chunk_tf32(
    const float* sAh, const float* sAl, const float* sBh, const float* sBl,
    float acc[2][4][4], int wm, int wn, int g, int t)
{
    #pragma unroll
    for (int kk = 0; kk < 4; kk++) {
        const int kc = kk * 8;
        uint32_t ah[2][4], al[2][4];
        #pragma unroll
        for (int mt = 0; mt < 2; mt++) {
            const int r0 = (wm * 32 + mt * 16 + g) * SA + kc + t;
            const int r1 = r0 + 8 * SA;
            ah[mt][0] = fu(sAh[r0]);     ah[mt][1] = fu(sAh[r1]);
            ah[mt][2] = fu(sAh[r0 + 4]); ah[mt][3] = fu(sAh[r1 + 4]);
            al[mt][0] = fu(sAl[r0]);     al[mt][1] = fu(sAl[r1]);
            al[mt][2] = fu(sAl[r0 + 4]); al[mt][3] = fu(sAl[r1 + 4]);
        }
        #pragma unroll
        for (int nt = 0; nt < 4; nt++) {
            const int nb = (wn * 32 + nt * 8 + g) * 36 + kc + t;
            const uint32_t bh0 = fu(sBh[nb]), bh1 = fu(sBh[nb + 4]);
            const uint32_t bl0 = fu(sBl[nb]), bl1 = fu(sBl[nb + 4]);
            #pragma unroll
            for (int mt = 0; mt < 2; mt++) {
                mma8_tf32(acc[mt][nt], ah[mt], bh0, bh1);
                mma8_tf32(acc[mt][nt], ah[mt], bl0, bl1);
                mma8_tf32(acc[mt][nt], al[mt], bh0, bh1);
            }
        }
    }
}

// grid (25, 32). M=128 pixels x N=64 clusters; contraction C=512, 16 chunks of 32.
// smem floats: sAh@0 (128*37), sAl@4736, sBh@9472 (64*36), sBl@11776,
// bias@14080; sL (128*65) overlays sAh/sAl in epilogue. Total 14144 floats.
#define G1_SMEM (14144 * 4)
__global__ __launch_bounds__(256, 2) void k_logits_tc(
    const float* __restrict__ x, const float* __restrict__ w,
    const float* __restrict__ bias)
{
    extern __shared__ float pool[];
    float* sAh = pool;
    float* sAl = pool + 4736;
    float* sBh = pool + 9472;
    float* sBl = pool + 11776;
    float* sBias = pool + 14080;
    float* sL = pool;                 // epilogue overlay [128][65]

    const int tid = threadIdx.x, lane = tid & 31, wid = tid >> 5;
    const int g = lane >> 2, t = lane & 3;
    const int wm = wid & 3, wn = wid >> 2;
    const int n = blockIdx.y, p0 = blockIdx.x * 128;

    if (tid < 64) sBias[tid] = bias[tid];

    const float* xn = x + (size_t)n * C * P;
    const int pl = tid & 127;
    const bool pok = (p0 + pl) < P;
    const int cb = tid >> 7;

    float acc[2][4][4];
    #pragma unroll
    for (int mt = 0; mt < 2; mt++)
        #pragma unroll
        for (int nt = 0; nt < 4; nt++)
            #pragma unroll
            for (int q = 0; q < 4; q++) acc[mt][nt][q] = 0.f;

    float xv[16], wv[8];
    #pragma unroll
    for (int r = 0; r < 16; r++)
        xv[r] = pok ? xn[(size_t)(cb + 2 * r) * P + p0 + pl] : 0.f;
    #pragma unroll
    for (int r = 0; r < 8; r++)
        wv[r] = w[(size_t)(wid + 8 * r) * C + lane];

    for (int i = 0; i < 16; i++) {
        if (i) __syncthreads();
        #pragma unroll
        for (int r = 0; r < 16; r++) {
            const int cc = cb + 2 * r;
            const float v = xv[r], h = tf32_rn(v);
            sAh[pl * 37 + cc] = h;
            sAl[pl * 37 + cc] = v - h;
        }
        #pragma unroll
        for (int r = 0; r < 8; r++) {
            const int k = wid + 8 * r;
            const float v = wv[r], h = tf32_rn(v);
            sBh[k * 36 + lane] = h;
            sBl[k * 36 + lane] = v - h;
        }
        __syncthreads();
        if (i + 1 < 16) {
            const int c0 = (i + 1) * 32;
            #pragma unroll
            for (int r = 0; r < 16; r++)
                xv[r] = pok ? xn[(size_t)(c0 + cb + 2 * r) * P + p0 + pl] : 0.f;
            #pragma unroll
            for (int r = 0; r < 8; r++)
                wv[r] = w[(size_t)(wid + 8 * r) * C + c0 + lane];
        }
        compute_chunk_tf32<37>(sAh, sAl, sBh, sBl, acc, wm, wn, g, t);
    }

    __syncthreads();
    #pragma unroll
    for (int mt = 0; mt < 2; mt++) {
        const int pr = wm * 32 + mt * 16 + g;
        #pragma unroll
        for (int nt = 0; nt < 4; nt++) {
            const int k0 = wn * 32 + nt * 8 + 2 * t;
            sL[pr * 65 + k0]           = acc[mt][nt][0] + sBias[k0];
            sL[pr * 65 + k0 + 1]       = acc[mt][nt][1] + sBias[k0 + 1];
            sL[(pr + 8) * 65 + k0]     = acc[mt][nt][2] + sBias[k0];
            sL[(pr + 8) * 65 + k0 + 1] = acc[mt][nt][3] + sBias[k0 + 1];
        }
    }
    __syncthreads();
    if (tid < 128 && p0 + tid < P) {
        const float* row = sL + tid * 65;
        float v[64], m = -1e30f;
        #pragma unroll
        for (int k = 0; k < 64; k++) { v[k] = row[k]; m = fmaxf(m, v[k]); }
        float s = 0.f;
        #pragma unroll
        for (int k = 0; k < 64; k++) { v[k] = __expf(v[k] - m); s += v[k]; }
        const float inv = 1.f / s;
        float* ga = g_a + (size_t)n * K * P + p0 + tid;
        #pragma unroll
        for (int k = 0; k < 64; k++) ga[(size_t)k * P] = v[k] * inv;
    }
}

// ===================== GEMM2: fp16 3x m16n8k16, vlad partials + fused asum ====
// Layout: rows of 40 halves (32 data + 8 pad) = 20 u32 words.
// Frag load word = row*20 + kk*8 + t  -> banks 20g+t: conflict-free.
#define XROW 40
#define XW   20
// halves: sXh 128*40, sXl 128*40, sPh 64*40, sPl 64*40 = 15360 halves
#define G2_SMEM (15360 * 2)
__global__ __launch_bounds__(256, 2) void k_vlad_tc(const float* __restrict__ x)
{
    extern __shared__ __half hpool[];
    __half* sXh = hpool;
    __half* sXl = hpool + 128 * XROW;
    __half* sPh = hpool + 256 * XROW;
    __half* sPl = hpool + 256 * XROW + 64 * XROW;
    const uint32_t* Xh32 = (const uint32_t*)sXh;
    const uint32_t* Xl32 = (const uint32_t*)sXl;
    const uint32_t* Ph32 = (const uint32_t*)sPh;
    const uint32_t* Pl32 = (const uint32_t*)sPl;

    const int tid = threadIdx.x, lane = tid & 31, wid = tid >> 5;
    const int g = lane >> 2, t = lane & 3;
    const int wm = wid & 3, wn = wid >> 2;
    const int n = blockIdx.z, sp = blockIdx.y, c0 = blockIdx.x * 128;
    const bool do_asum = (blockIdx.x == 0);

    const float* xn = x + ((size_t)n * C + c0) * P;
    const float* an = g_a + (size_t)n * K * P;
    const int pb0 = sp * PCH;

    float acc[2][4][4];
    #pragma unroll
    for (int mt = 0; mt < 2; mt++)
        #pragma unroll
        for (int nt = 0; nt < 4; nt++)
            #pragma unroll
            for (int q = 0; q < 4; q++) acc[mt][nt][q] = 0.f;

    float asumL[8];
    #pragma unroll
    for (int r = 0; r < 8; r++) asumL[r] = 0.f;

    float xv[16], av[8];
    #pragma unroll
    for (int r = 0; r < 16; r++)
        xv[r] = xn[(size_t)(wid + 8 * r) * P + pb0 + lane];
    #pragma unroll
    for (int r = 0; r < 8; r++)
        av[r] = an[(size_t)(wid + 8 * r) * P + pb0 + lane];

    for (int i = 0; i < 49; i++) {
        if (i) __syncthreads();
        #pragma unroll
        for (int r = 0; r < 16; r++) {
            const int row = wid + 8 * r;
            const float v = xv[r];
            const __half h = __float2half_rn(v);
            sXh[row * XROW + lane] = h;
            sXl[row * XROW + lane] = __float2half_rn(v - __half2float(h));
        }
        #pragma unroll
        for (int r = 0; r < 8; r++) {
            const int row = wid + 8 * r;
            const float v = av[r];
            const __half h = __float2half_rn(v);
            sPh[row * XROW + lane] = h;
            sPl[row * XROW + lane] = __float2half_rn(v - __half2float(h));
            if (do_asum) asumL[r] += v;
        }
        __syncthreads();
        if (i + 1 < 49) {
            const int pb = pb0 + (i + 1) * 32;
            #pragma unroll
            for (int r = 0; r < 16; r++)
                xv[r] = xn[(size_t)(wid + 8 * r) * P + pb + lane];
            #pragma unroll
            for (int r = 0; r < 8; r++)
                av[r] = an[(size_t)(wid + 8 * r) * P + pb + lane];
        }
        // compute: 2 k16 blocks
        #pragma unroll
        for (int kk = 0; kk < 2; kk++) {
            uint32_t ah[2][4], al[2][4];
            #pragma unroll
            for (int mt = 0; mt < 2; mt++) {
                const int r0 = (wm * 32 + mt * 16 + g) * XW + kk * 8 + t;
                const int r1 = r0 + 8 * XW;
                ah[mt][0] = Xh32[r0];     ah[mt][1] = Xh32[r1];
                ah[mt][2] = Xh32[r0 + 4]; ah[mt][3] = Xh32[r1 + 4];
                al[mt][0] = Xl32[r0];     al[mt][1] = Xl32[r1];
                al[mt][2] = Xl32[r0 + 4]; al[mt][3] = Xl32[r1 + 4];
            }
            #pragma unroll
            for (int nt = 0; nt < 4; nt++) {
                const int nb = (wn * 32 + nt * 8 + g) * XW + kk * 8 + t;
                const uint32_t bh0 = Ph32[nb], bh1 = Ph32[nb + 4];
                const uint32_t bl0 = Pl32[nb], bl1 = Pl32[nb + 4];
                #pragma unroll
                for (int mt = 0; mt < 2; mt++) {
                    mma16_f16(acc[mt][nt], ah[mt][0], ah[mt][1], ah[mt][2], ah[mt][3], bh0, bh1);
                    mma16_f16(acc[mt][nt], ah[mt][0], ah[mt][1], ah[mt][2], ah[mt][3], bl0, bl1);
                    mma16_f16(acc[mt][nt], al[mt][0], al[mt][1], al[mt][2], al[mt][3], bh0, bh1);
                }
            }
        }
    }

    float* gp = g_part + ((size_t)sp * NB + n) * CK;
    #pragma unroll
    for (int mt = 0; mt < 2; mt++) {
        const int cr = c0 + wm * 32 + mt * 16 + g;
        #pragma unroll
        for (int nt = 0; nt < 4; nt++) {
            const int k0 = wn * 32 + nt * 8 + 2 * t;
            *(float2*)(gp + (size_t)cr * 64 + k0) =
                make_float2(acc[mt][nt][0], acc[mt][nt][1]);
            *(float2*)(gp + (size_t)(cr + 8) * 64 + k0) =
                make_float2(acc[mt][nt][2], acc[mt][nt][3]);
        }
    }

    if (do_asum) {
        #pragma unroll
        for (int r = 0; r < 8; r++) {
            float s = asumL[r];
            #pragma unroll
            for (int o = 16; o > 0; o >>= 1) s += __shfl_xor_sync(0xffffffffu, s, o);
            if (lane == 0) g_asumP[(sp * NB + n) * K + wid + 8 * r] = s;
        }
    }
}

// --------------- combine partials + centroid correction + intra-norm
__global__ __launch_bounds__(256) void k_combine_intra(
    const float* __restrict__ cent, float* __restrict__ out)
{
    const int row = blockIdx.x * 8 + (threadIdx.x >> 5);   // n*512 + c
    const int n = row >> 9, c = row & 511;
    const int lane = threadIdx.x & 31;

    const size_t b0 = (size_t)n * CK + c * 64;
    const size_t b1 = ((size_t)NB + n) * CK + c * 64;

    float v0 = g_part[b0 + lane] + g_part[b1 + lane]
             - cent[c * 64 + lane]
               * (g_asumP[n * K + lane] + g_asumP[(NB + n) * K + lane]);
    float v1 = g_part[b0 + lane + 32] + g_part[b1 + lane + 32]
             - cent[c * 64 + lane + 32]
               * (g_asumP[n * K + lane + 32] + g_asumP[(NB + n) * K + lane + 32]);

    float sq = v0 * v0 + v1 * v1;
    #pragma unroll
    for (int o = 16; o > 0; o >>= 1) sq += __shfl_xor_sync(0xffffffffu, sq, o);

    const float denom = fmaxf(sqrtf(sq), 1e-12f);
    const float inv = 1.f / denom;
    out[(size_t)n * CK + c * 64 + lane]      = v0 * inv;
    out[(size_t)n * CK + c * 64 + lane + 32] = v1 * inv;
    if (lane == 0) g_rowsq[row] = sq * inv * inv;
}

// --------------------- global norm: reduce then scale
__global__ __launch_bounds__(256) void k_norm() {
    const int n = blockIdx.x;
    const int t = threadIdx.x;
    __shared__ float red[256];
    red[t] = g_rowsq[n * 512 + t] + g_rowsq[n * 512 + 256 + t];
    __syncthreads();
    for (int o = 128; o > 0; o >>= 1) {
        if (t < o) red[t] += red[t + o];
        __syncthreads();
    }
    if (t == 0) g_inv[n] = 1.f / fmaxf(sqrtf(red[0]), 1e-12f);
}

__global__ __launch_bounds__(256) void k_scale(float* __restrict__ out) {
    const int n = blockIdx.y;
    const float inv = g_inv[n];
    float4* v = (float4*)(out + (size_t)n * CK + blockIdx.x * 4096);
    const int t = threadIdx.x;
    #pragma unroll
    for (int j = 0; j < 4; j++) {
        float4 u = v[t + 256 * j];
        u.x *= inv; u.y *= inv; u.z *= inv; u.w *= inv;
        v[t + 256 * j] = u;
    }
}

extern "C" void kernel_launch(void* const* d_in, const int* in_sizes, int n_in,
                              void* d_out, int out_size) {
    const float* x    = (const float*)d_in[0];   // (32,512,56,56)
    const float* cent = (const float*)d_in[1];   // (64,512)
    const float* w    = (const float*)d_in[2];   // (64,512)
    const float* b    = (const float*)d_in[3];   // (64,)
    float* out = (float*)d_out;                  // (32, 32768)

    cudaFuncSetAttribute(k_logits_tc, cudaFuncAttributeMaxDynamicSharedMemorySize, G1_SMEM);
    cudaFuncSetAttribute(k_vlad_tc,   cudaFuncAttributeMaxDynamicSharedMemorySize, G2_SMEM);

    k_logits_tc<<<dim3(25, 32), 256, G1_SMEM>>>(x, w, b);
    k_vlad_tc<<<dim3(4, PSPLIT, NB), 256, G2_SMEM>>>(x);
    k_combine_intra<<<NB * C / 8, 256>>>(cent, out);
    k_norm<<<NB, 256>>>();
    k_scale<<<dim3(8, NB), 256>>>(out);
}